// round 11
// baseline (speedup 1.0000x reference)
#include <cuda_runtime.h>
#include <cuda_fp16.h>
#include <cstdint>
#include <cstddef>

#define N_DIM     512
#define BATCH_DIM 16384
#define NROUND    511
#define NPAIR     256
#define RPB       4                 // rows per build block
#define NSEG      4                 // rounds split: [0,128),[128,256),[256,384),[384,511)

// ---------------- scratch (static device globals; no runtime allocation) ----------------
__device__ __align__(16) uint32_t g_sched[NROUND * NPAIR];   // packed (i | j<<16), oriented
__device__ __align__(16) float2   g_cs  [NROUND * NPAIR];    // matching (cos, sin')
__device__ __align__(16) float    g_V[NSEG][N_DIM * N_DIM];  // per-segment products
__device__ __align__(16) float    g_W0[N_DIM * N_DIM];       // V0*V1
__device__ __align__(16) float    g_W1[N_DIM * N_DIM];       // V2*V3
__device__ __align__(16) __half   g_Uh[N_DIM * N_DIM];       // U = W0*W1, fp16
__device__ __align__(16) __half   g_xh[(size_t)BATCH_DIM * N_DIM];

// ---------------- helpers ----------------
__device__ __forceinline__ uint32_t smem_u32(const void* p) {
    uint32_t a;
    asm("{ .reg .u64 t; cvta.to.shared.u64 t, %1; cvt.u32.u64 %0, t; }" : "=r"(a) : "l"(p));
    return a;
}

__device__ __forceinline__ void cp_async16(uint32_t s, const void* g) {
    asm volatile("cp.async.cg.shared.global [%0], [%1], 16;" :: "r"(s), "l"(g) : "memory");
}

__device__ __forceinline__ void ldm_x4(uint32_t* r, uint32_t addr) {
    asm volatile("ldmatrix.sync.aligned.m8n8.x4.shared.b16 {%0,%1,%2,%3}, [%4];"
                 : "=r"(r[0]), "=r"(r[1]), "=r"(r[2]), "=r"(r[3]) : "r"(addr));
}

__device__ __forceinline__ void mma16816(float* d, const uint32_t* a, uint32_t b0, uint32_t b1) {
    asm volatile(
        "mma.sync.aligned.m16n8k16.row.col.f32.f16.f16.f32 "
        "{%0,%1,%2,%3}, {%4,%5,%6,%7}, {%8,%9}, {%0,%1,%2,%3};"
        : "+f"(d[0]), "+f"(d[1]), "+f"(d[2]), "+f"(d[3])
        : "r"(a[0]), "r"(a[1]), "r"(a[2]), "r"(a[3]), "r"(b0), "r"(b1));
}

// ---------------- kernel 1: conflict-aware scheduling + sincos ----------------
__global__ void __launch_bounds__(NPAIR) sched_kernel(const int* __restrict__ blocks,
                                                      const float* __restrict__ angles) {
    __shared__ int  cnt[32];
    __shared__ int  jflag[8 * 32];
    __shared__ unsigned char taken[NPAIR];
    __shared__ int  sfree[NPAIR];
    __shared__ int  nfree, ovfp;
    const int r = blockIdx.x;
    const int t = threadIdx.x;
    if (t < 32) cnt[t] = 0;
    jflag[t] = 0;
    taken[t] = 0;
    if (t == 0) { nfree = 0; ovfp = 0; }
    __syncthreads();

    const int i = blocks[(r * NPAIR + t) * 2];
    const int j = blocks[(r * NPAIR + t) * 2 + 1];
    float s, c;
    sincosf(angles[r * NPAIR + t], &s, &c);
    const int bi = i & 31, bj = j & 31;

    const int oA = cnt[bi], oB = cnt[bj];
    const int fA = (oA < 8) && (jflag[oA * 32 + bj] == 0);
    const int fB = (oB < 8) && (jflag[oB * 32 + bi] == 0);
    int pref_first;
    if (fA != fB) pref_first = fA;
    else          pref_first = (oA <= oB);

    int slot = -1, swapped = 0;
    const int b0 = pref_first ? bi : bj;
    const int jb0 = pref_first ? bj : bi;
    int occ = atomicAdd(&cnt[b0], 1);
    if (occ < 8) {
        slot = occ * 32 + b0; swapped = pref_first ? 0 : 1;
        jflag[occ * 32 + jb0] = 1;
    } else {
        atomicSub(&cnt[b0], 1);
        const int b1 = pref_first ? bj : bi;
        const int jb1 = pref_first ? bi : bj;
        occ = atomicAdd(&cnt[b1], 1);
        if (occ < 8) {
            slot = occ * 32 + b1; swapped = pref_first ? 1 : 0;
            jflag[occ * 32 + jb1] = 1;
        } else atomicSub(&cnt[b1], 1);
    }
    if (slot >= 0) taken[slot] = 1;
    __syncthreads();
    if (!taken[t]) { int k = atomicAdd(&nfree, 1); sfree[k] = t; }
    __syncthreads();
    if (slot < 0) { int k = atomicAdd(&ovfp, 1); slot = sfree[k]; }

    const uint32_t ii = (uint32_t)(swapped ? j : i);
    const uint32_t jj = (uint32_t)(swapped ? i : j);
    g_sched[r * NPAIR + slot] = ii | (jj << 16);
    g_cs  [r * NPAIR + slot] = make_float2(c, swapped ? -s : s);
}

// ---------------- kernel 2 (fused): build V_seg rows (4 segs)  +  cast x to fp16 ----------------
// Blocks [0,512): seg = bid>>7 builds rounds [seg*128, min((seg+1)*128, 511)) -> g_V[seg].
// Blocks [512,768): cast x -> fp16.
__global__ void __launch_bounds__(256) build_split_kernel(const float4* __restrict__ x4) {
    const int t = threadIdx.x;
    if (blockIdx.x < 512) {
        __shared__ float rows[RPB][N_DIM];
        const int seg   = blockIdx.x >> 7;                  // 0..3
        const int obase = (blockIdx.x & 127) * RPB;
        const int r0 = seg * 128;
        const int r1 = (seg == NSEG - 1) ? NROUND : (r0 + 128);
        float* __restrict__ Vout = g_V[seg];
        #pragma unroll
        for (int q = 0; q < RPB; q++) {
            rows[q][t]       = (t == obase + q)       ? 1.0f : 0.0f;
            rows[q][t + 256] = (t + 256 == obase + q) ? 1.0f : 0.0f;
        }
        uint32_t id = g_sched[r0 * NPAIR + t];
        float2   cs = g_cs[r0 * NPAIR + t];
        __syncthreads();
        for (int r = r0; r < r1; r++) {
            const int nidx = (r + 1 < r1) ? (r + 1) * NPAIR + t : r0 * NPAIR + t;
            const uint32_t id_n = g_sched[nidx];
            const float2   cs_n = g_cs[nidx];
            const int i = (int)(id & 0xFFFFu);
            const int j = (int)(id >> 16);
            #pragma unroll
            for (int q = 0; q < RPB; q++) {
                const float ui = rows[q][i];
                const float uj = rows[q][j];
                rows[q][i] = fmaf(cs.x, ui, cs.y * uj);
                rows[q][j] = fmaf(cs.x, uj, -(cs.y * ui));
            }
            __syncthreads();
            id = id_n; cs = cs_n;
        }
        #pragma unroll
        for (int q = 0; q < RPB; q++)
            for (int c = t; c < N_DIM; c += 256)
                Vout[(obase + q) * N_DIM + c] = rows[q][c];
    } else {
        // cast x -> fp16
        const int bs = blockIdx.x - 512;                    // 0..255
        const int base = bs * 8192;                         // 256*8192 = 2^21 float4 exact
        #pragma unroll 4
        for (int k = 0; k < 32; k++) {
            const int idx = base + k * 256 + t;
            const float4 v = x4[idx];
            __half2 a, b;
            a.x = __float2half(v.x); a.y = __float2half(v.y);
            b.x = __float2half(v.z); b.y = __float2half(v.w);
            ((__half2*)g_xh)[2 * idx]     = a;
            ((__half2*)g_xh)[2 * idx + 1] = b;
        }
    }
}

// ---------------- fixup GEMM core: C[m,n] = sum_k A[m,k] * B[k,n]  (fp32, 512^3) ----------------
template <typename OutT>
__device__ __forceinline__ void fixup_body(const float* __restrict__ A,
                                           const float* __restrict__ B,
                                           OutT* __restrict__ C) {
    __shared__ float As[32][33];    // [m][k]
    __shared__ float Bs[32][65];    // [k][n]
    const int tid = threadIdx.x;
    const int tx = tid & 15;        // n group -> 4 cols
    const int ty = tid >> 4;        // m group -> 4 rows
    const int n0 = blockIdx.x * 64;
    const int m0 = blockIdx.y * 32;
    float acc[4][4] = {};
    for (int kc = 0; kc < N_DIM; kc += 32) {
        #pragma unroll
        for (int l = 0; l < 8; l++) {                       // A: 32x32
            const int idx = tid + l * 128;
            const int row = idx >> 5, k = idx & 31;
            As[row][k] = A[(m0 + row) * N_DIM + kc + k];
        }
        #pragma unroll
        for (int l = 0; l < 16; l++) {                      // B: 32x64
            const int idx = tid + l * 128;
            const int k = idx >> 6, col = idx & 63;
            Bs[k][col] = B[(kc + k) * N_DIM + n0 + col];
        }
        __syncthreads();
        #pragma unroll 8
        for (int kk = 0; kk < 32; kk++) {
            float a[4], b[4];
            #pragma unroll
            for (int i = 0; i < 4; i++) a[i] = As[ty * 4 + i][kk];
            #pragma unroll
            for (int i = 0; i < 4; i++) b[i] = Bs[kk][tx * 4 + i];
            #pragma unroll
            for (int i = 0; i < 4; i++)
                #pragma unroll
                for (int j = 0; j < 4; j++)
                    acc[i][j] = fmaf(a[i], b[j], acc[i][j]);
        }
        __syncthreads();
    }
    #pragma unroll
    for (int i = 0; i < 4; i++)
        #pragma unroll
        for (int j = 0; j < 4; j++) {
            const float v = acc[i][j];
            OutT o;
            if constexpr (sizeof(OutT) == 2) o = __float2half(v);
            else                             o = v;
            C[(m0 + ty * 4 + i) * N_DIM + n0 + tx * 4 + j] = o;
        }
}

// level 1: W0 = V0*V1, W1 = V2*V3 (blockIdx.z selects)
__global__ void __launch_bounds__(128) fixup1_kernel() {
    if (blockIdx.z == 0) fixup_body<float>(g_V[0], g_V[1], g_W0);
    else                 fixup_body<float>(g_V[2], g_V[3], g_W1);
}
// level 2: U = W0*W1, cast fp16
__global__ void __launch_bounds__(128) fixup2_kernel() {
    fixup_body<__half>(g_W0, g_W1, g_Uh);
}

// ---------------- kernel 4: single fp16 GEMM out = x @ U^T + bias ----------------
#define KC        64
#define PITCH     144
#define TILE_SB   (128 * PITCH)             // 18432 B
#define STAGE_SB  (2 * TILE_SB)             // A + B = 36864 B
#define NSTAGE    3
#define GEMM_SMEM (NSTAGE * STAGE_SB)       // 110592 B
#define NCHUNK    8

__device__ __forceinline__ void issue_chunk(uint32_t sbase, int i, int m0, int n0, int tid) {
    if (i < NCHUNK) {
        const __half* gA = g_xh + (size_t)m0 * N_DIM + i * KC;
        const __half* gB = g_Uh + (size_t)n0 * N_DIM + i * KC;
        const uint32_t stage = sbase + (uint32_t)(i % NSTAGE) * STAGE_SB;
        #pragma unroll
        for (int tt = 0; tt < 4; tt++) {                    // each tile: 1024 x 16B
            const int idx = tid + tt * 256;
            const int row = idx >> 3, seg = idx & 7;
            const uint32_t soff = (uint32_t)(row * PITCH + seg * 16);
            const size_t goff = (size_t)row * N_DIM + seg * 8;
            cp_async16(stage + soff,           gA + goff);
            cp_async16(stage + TILE_SB + soff, gB + goff);
        }
    }
    asm volatile("cp.async.commit_group;" ::: "memory");
}

__global__ void __launch_bounds__(256, 2) gemm_kernel(float* __restrict__ out,
                                                      const float* __restrict__ bias) {
    extern __shared__ char smem[];
    const uint32_t sb = smem_u32(smem);
    const int tid   = threadIdx.x;
    const int lane  = tid & 31;
    const int wid   = tid >> 5;
    const int warpM = wid & 3;
    const int warpN = wid >> 2;
    const int n0 = blockIdx.x * 128;
    const int m0 = blockIdx.y * 128;

    float acc[2][8][4];
    #pragma unroll
    for (int a = 0; a < 2; a++)
        #pragma unroll
        for (int b = 0; b < 8; b++)
            #pragma unroll
            for (int c = 0; c < 4; c++) acc[a][b][c] = 0.0f;

    const int lrow = lane & 15;
    const int loct = lane >> 4;

    issue_chunk(sb, 0, m0, n0, tid);
    issue_chunk(sb, 1, m0, n0, tid);

    for (int i = 0; i < NCHUNK; i++) {
        issue_chunk(sb, i + 2, m0, n0, tid);
        asm volatile("cp.async.wait_group 2;" ::: "memory");
        __syncthreads();

        const uint32_t stage = sb + (uint32_t)(i % NSTAGE) * STAGE_SB;
        const uint32_t sA = stage + (uint32_t)((warpM * 32 + lrow) * PITCH);
        const uint32_t sB = stage + TILE_SB + (uint32_t)((warpN * 64 + lrow) * PITCH);

        #pragma unroll
        for (int ks = 0; ks < 4; ks++) {
            const uint32_t koff = (uint32_t)(ks * 32 + loct * 16);
            uint32_t afr[2][4], bfr[4][4];
            #pragma unroll
            for (int mi = 0; mi < 2; mi++)
                ldm_x4(afr[mi], sA + (uint32_t)(mi * 16 * PITCH) + koff);
            #pragma unroll
            for (int nj = 0; nj < 4; nj++)
                ldm_x4(bfr[nj], sB + (uint32_t)(nj * 16 * PITCH) + koff);
            #pragma unroll
            for (int mi = 0; mi < 2; mi++)
                #pragma unroll
                for (int t = 0; t < 8; t++) {
                    const int nj = t >> 1, hl = t & 1;
                    mma16816(acc[mi][t], afr[mi], bfr[nj][hl], bfr[nj][hl + 2]);
                }
        }
        __syncthreads();
    }

    const int rbase = m0 + warpM * 32 + (lane >> 2);
    const int cbase = n0 + warpN * 64 + (lane & 3) * 2;
    #pragma unroll
    for (int t = 0; t < 8; t++) {
        const int col = cbase + t * 8;
        const float2 bv = __ldg((const float2*)&bias[col]);
        #pragma unroll
        for (int mi = 0; mi < 2; mi++) {
            const int r0 = rbase + mi * 16;
            float2 v0, v1;
            v0.x = acc[mi][t][0] + bv.x; v0.y = acc[mi][t][1] + bv.y;
            v1.x = acc[mi][t][2] + bv.x; v1.y = acc[mi][t][3] + bv.y;
            *(float2*)&out[(size_t)r0 * N_DIM + col]       = v0;
            *(float2*)&out[(size_t)(r0 + 8) * N_DIM + col] = v1;
        }
    }
}

// ---------------- launch ----------------
extern "C" void kernel_launch(void* const* d_in, const int* in_sizes, int n_in,
                              void* d_out, int out_size) {
    const float* x = nullptr;
    const float* angles = nullptr;
    const float* bias = nullptr;
    const int*   blocks = nullptr;
    for (int i = 0; i < n_in; i++) {
        const long sz = in_sizes[i];
        if      (sz == (long)BATCH_DIM * N_DIM)  x      = (const float*)d_in[i];
        else if (sz == (long)NROUND * NPAIR)     angles = (const float*)d_in[i];
        else if (sz == (long)N_DIM)              bias   = (const float*)d_in[i];
        else if (sz == (long)NROUND * NPAIR * 2) blocks = (const int*)d_in[i];
    }
    float* out = (float*)d_out;

    sched_kernel<<<NROUND, NPAIR>>>(blocks, angles);
    build_split_kernel<<<768, 256>>>((const float4*)x);
    fixup1_kernel<<<dim3(N_DIM / 64, N_DIM / 32, 2), 128>>>();
    fixup2_kernel<<<dim3(N_DIM / 64, N_DIM / 32, 1), 128>>>();
    cudaFuncSetAttribute(gemm_kernel, cudaFuncAttributeMaxDynamicSharedMemorySize, GEMM_SMEM);
    gemm_kernel<<<dim3(4, 128), 256, GEMM_SMEM>>>(out, bias);
}

// round 14
// speedup vs baseline: 1.2471x; 1.2471x over previous
#include <cuda_runtime.h>
#include <cuda_fp16.h>
#include <cstdint>
#include <cstddef>

#define N_DIM     512
#define BATCH_DIM 16384
#define NROUND    511
#define NPAIR     256
#define RPB       4                 // rows per build block
#define SEG0_END  256               // seg0 = rounds [0,256), seg1 = [256,511)

// ---------------- scratch (static device globals; no runtime allocation) ----------------
__device__ __align__(16) uint32_t g_sched[NROUND * NPAIR];   // packed (i | j<<16), oriented
__device__ __align__(16) float2   g_cs  [NROUND * NPAIR];    // matching (cos, sin')
__device__ __align__(16) __half   g_V0h [N_DIM * N_DIM];     // V0, fp16, (m,k) K-major
__device__ __align__(16) __half   g_V1Th[N_DIM * N_DIM];     // V1^T, fp16: [n*512+k] = V1[k][n]
__device__ __align__(16) __half   g_Uh  [N_DIM * N_DIM];     // U = V0*V1, fp16 row-major
__device__ __align__(16) __half   g_xh[(size_t)BATCH_DIM * N_DIM];

// ---------------- helpers ----------------
__device__ __forceinline__ uint32_t smem_u32(const void* p) {
    uint32_t a;
    asm("{ .reg .u64 t; cvta.to.shared.u64 t, %1; cvt.u32.u64 %0, t; }" : "=r"(a) : "l"(p));
    return a;
}

__device__ __forceinline__ void cp_async16(uint32_t s, const void* g) {
    asm volatile("cp.async.cg.shared.global [%0], [%1], 16;" :: "r"(s), "l"(g) : "memory");
}

__device__ __forceinline__ void ldm_x4(uint32_t* r, uint32_t addr) {
    asm volatile("ldmatrix.sync.aligned.m8n8.x4.shared.b16 {%0,%1,%2,%3}, [%4];"
                 : "=r"(r[0]), "=r"(r[1]), "=r"(r[2]), "=r"(r[3]) : "r"(addr));
}

__device__ __forceinline__ void mma16816(float* d, const uint32_t* a, uint32_t b0, uint32_t b1) {
    asm volatile(
        "mma.sync.aligned.m16n8k16.row.col.f32.f16.f16.f32 "
        "{%0,%1,%2,%3}, {%4,%5,%6,%7}, {%8,%9}, {%0,%1,%2,%3};"
        : "+f"(d[0]), "+f"(d[1]), "+f"(d[2]), "+f"(d[3])
        : "r"(a[0]), "r"(a[1]), "r"(a[2]), "r"(a[3]), "r"(b0), "r"(b1));
}

// ---------------- kernel 1: conflict-aware scheduling + sincos ----------------
__global__ void __launch_bounds__(NPAIR) sched_kernel(const int* __restrict__ blocks,
                                                      const float* __restrict__ angles) {
    __shared__ int  cnt[32];
    __shared__ int  jflag[8 * 32];
    __shared__ unsigned char taken[NPAIR];
    __shared__ int  sfree[NPAIR];
    __shared__ int  nfree, ovfp;
    const int r = blockIdx.x;
    const int t = threadIdx.x;
    if (t < 32) cnt[t] = 0;
    jflag[t] = 0;
    taken[t] = 0;
    if (t == 0) { nfree = 0; ovfp = 0; }
    __syncthreads();

    const int i = blocks[(r * NPAIR + t) * 2];
    const int j = blocks[(r * NPAIR + t) * 2 + 1];
    float s, c;
    sincosf(angles[r * NPAIR + t], &s, &c);
    const int bi = i & 31, bj = j & 31;

    const int oA = cnt[bi], oB = cnt[bj];
    const int fA = (oA < 8) && (jflag[oA * 32 + bj] == 0);
    const int fB = (oB < 8) && (jflag[oB * 32 + bi] == 0);
    int pref_first;
    if (fA != fB) pref_first = fA;
    else          pref_first = (oA <= oB);

    int slot = -1, swapped = 0;
    const int b0 = pref_first ? bi : bj;
    const int jb0 = pref_first ? bj : bi;
    int occ = atomicAdd(&cnt[b0], 1);
    if (occ < 8) {
        slot = occ * 32 + b0; swapped = pref_first ? 0 : 1;
        jflag[occ * 32 + jb0] = 1;
    } else {
        atomicSub(&cnt[b0], 1);
        const int b1 = pref_first ? bj : bi;
        const int jb1 = pref_first ? bi : bj;
        occ = atomicAdd(&cnt[b1], 1);
        if (occ < 8) {
            slot = occ * 32 + b1; swapped = pref_first ? 1 : 0;
            jflag[occ * 32 + jb1] = 1;
        } else atomicSub(&cnt[b1], 1);
    }
    if (slot >= 0) taken[slot] = 1;
    __syncthreads();
    if (!taken[t]) { int k = atomicAdd(&nfree, 1); sfree[k] = t; }
    __syncthreads();
    if (slot < 0) { int k = atomicAdd(&ovfp, 1); slot = sfree[k]; }

    const uint32_t ii = (uint32_t)(swapped ? j : i);
    const uint32_t jj = (uint32_t)(swapped ? i : j);
    g_sched[r * NPAIR + slot] = ii | (jj << 16);
    g_cs  [r * NPAIR + slot] = make_float2(c, swapped ? -s : s);
}

// ---------------- kernel 2 (fused): build V0 / V1^T (fp16)  +  cast x to fp16 ----------------
// Blocks [0,128):   seg0 rounds [0,256)   -> g_V0h  (K-major rows)
// Blocks [128,256): seg1 rounds [256,511) -> g_V1Th (transposed: [n][k] = V1[k][n])
// Blocks [256,512): cast x -> fp16.
__global__ void __launch_bounds__(256) build_split_kernel(const float4* __restrict__ x4) {
    const int t = threadIdx.x;
    if (blockIdx.x < 256) {
        __shared__ float rows[RPB][N_DIM];
        const int seg   = blockIdx.x >> 7;                  // 0 or 1
        const int obase = (blockIdx.x & 127) * RPB;
        const int r0 = seg ? SEG0_END : 0;
        const int r1 = seg ? NROUND   : SEG0_END;
        #pragma unroll
        for (int q = 0; q < RPB; q++) {
            rows[q][t]       = (t == obase + q)       ? 1.0f : 0.0f;
            rows[q][t + 256] = (t + 256 == obase + q) ? 1.0f : 0.0f;
        }
        uint32_t id = g_sched[r0 * NPAIR + t];
        float2   cs = g_cs[r0 * NPAIR + t];
        __syncthreads();
        for (int r = r0; r < r1; r++) {
            const int nidx = (r + 1 < r1) ? (r + 1) * NPAIR + t : r0 * NPAIR + t;
            const uint32_t id_n = g_sched[nidx];
            const float2   cs_n = g_cs[nidx];
            const int i = (int)(id & 0xFFFFu);
            const int j = (int)(id >> 16);
            #pragma unroll
            for (int q = 0; q < RPB; q++) {
                const float ui = rows[q][i];
                const float uj = rows[q][j];
                rows[q][i] = fmaf(cs.x, ui, cs.y * uj);
                rows[q][j] = fmaf(cs.x, uj, -(cs.y * ui));
            }
            __syncthreads();
            id = id_n; cs = cs_n;
        }
        if (seg == 0) {
            // V0 rows, K-major fp16
            #pragma unroll
            for (int q = 0; q < RPB; q++)
                for (int c = t; c < N_DIM; c += 256)
                    g_V0h[(obase + q) * N_DIM + c] = __float2half(rows[q][c]);
        } else {
            // V1 transposed: g_V1Th[c*512 + obase .. obase+3] = rows[0..3][c]
            #pragma unroll
            for (int cc = t; cc < N_DIM; cc += 256) {
                __half2 p0, p1;
                p0.x = __float2half(rows[0][cc]); p0.y = __float2half(rows[1][cc]);
                p1.x = __float2half(rows[2][cc]); p1.y = __float2half(rows[3][cc]);
                __half2* dst = (__half2*)&g_V1Th[cc * N_DIM + obase];
                dst[0] = p0; dst[1] = p1;
            }
        }
    } else {
        // cast x -> fp16
        const int bs = blockIdx.x - 256;                    // 0..255
        const int base = bs * 8192;                         // 256*8192 = 2^21 float4 exact
        #pragma unroll 4
        for (int k = 0; k < 32; k++) {
            const int idx = base + k * 256 + t;
            const float4 v = x4[idx];
            __half2 a, b;
            a.x = __float2half(v.x); a.y = __float2half(v.y);
            b.x = __float2half(v.z); b.y = __float2half(v.w);
            ((__half2*)g_xh)[2 * idx]     = a;
            ((__half2*)g_xh)[2 * idx + 1] = b;
        }
    }
}

// ---------------- shared HMMA tile machinery ----------------
#define KC        64
#define PITCH     144
#define TILE_SB   (128 * PITCH)             // 18432 B
#define STAGE_SB  (2 * TILE_SB)             // A + B = 36864 B
#define NSTAGE    3
#define GEMM_SMEM (NSTAGE * STAGE_SB)       // 110592 B
#define NCHUNK    8

__device__ __forceinline__ void issue_chunk_gen(uint32_t sbase, int i, int m0, int n0, int tid,
                                                const __half* __restrict__ Abuf,
                                                const __half* __restrict__ Bbuf) {
    if (i < NCHUNK) {
        const __half* gA = Abuf + (size_t)m0 * N_DIM + i * KC;
        const __half* gB = Bbuf + (size_t)n0 * N_DIM + i * KC;
        const uint32_t stage = sbase + (uint32_t)(i % NSTAGE) * STAGE_SB;
        #pragma unroll
        for (int tt = 0; tt < 4; tt++) {                    // each tile: 1024 x 16B
            const int idx = tid + tt * 256;
            const int row = idx >> 3, seg = idx & 7;
            const uint32_t soff = (uint32_t)(row * PITCH + seg * 16);
            const size_t goff = (size_t)row * N_DIM + seg * 8;
            cp_async16(stage + soff,           gA + goff);
            cp_async16(stage + TILE_SB + soff, gB + goff);
        }
    }
    asm volatile("cp.async.commit_group;" ::: "memory");
}

// Computes acc[2][8][4] = A[m0:+128,:] * B[n0:+128,:]^T over K=512.
__device__ __forceinline__ void hmma_tile(uint32_t sb, int m0, int n0, int tid,
                                          const __half* __restrict__ Abuf,
                                          const __half* __restrict__ Bbuf,
                                          float acc[2][8][4]) {
    const int lane  = tid & 31;
    const int wid   = tid >> 5;
    const int warpM = wid & 3;
    const int warpN = wid >> 2;
    const int lrow = lane & 15;
    const int loct = lane >> 4;

    issue_chunk_gen(sb, 0, m0, n0, tid, Abuf, Bbuf);
    issue_chunk_gen(sb, 1, m0, n0, tid, Abuf, Bbuf);

    for (int i = 0; i < NCHUNK; i++) {
        issue_chunk_gen(sb, i + 2, m0, n0, tid, Abuf, Bbuf);
        asm volatile("cp.async.wait_group 2;" ::: "memory");
        __syncthreads();

        const uint32_t stage = sb + (uint32_t)(i % NSTAGE) * STAGE_SB;
        const uint32_t sA = stage + (uint32_t)((warpM * 32 + lrow) * PITCH);
        const uint32_t sB = stage + TILE_SB + (uint32_t)((warpN * 64 + lrow) * PITCH);

        #pragma unroll
        for (int ks = 0; ks < 4; ks++) {
            const uint32_t koff = (uint32_t)(ks * 32 + loct * 16);
            uint32_t afr[2][4], bfr[4][4];
            #pragma unroll
            for (int mi = 0; mi < 2; mi++)
                ldm_x4(afr[mi], sA + (uint32_t)(mi * 16 * PITCH) + koff);
            #pragma unroll
            for (int nj = 0; nj < 4; nj++)
                ldm_x4(bfr[nj], sB + (uint32_t)(nj * 16 * PITCH) + koff);
            #pragma unroll
            for (int mi = 0; mi < 2; mi++)
                #pragma unroll
                for (int t = 0; t < 8; t++) {
                    const int nj = t >> 1, hl = t & 1;
                    mma16816(acc[mi][t], afr[mi], bfr[nj][hl], bfr[nj][hl + 2]);
                }
        }
        __syncthreads();
    }
}

// ---------------- kernel 3: fixup  U = V0 * V1  via HMMA (16 CTAs) ----------------
__global__ void __launch_bounds__(256, 2) fixup_kernel() {
    extern __shared__ char smem[];
    const uint32_t sb = smem_u32(smem);
    const int tid = threadIdx.x;
    const int lane = tid & 31;
    const int wid  = tid >> 5;
    const int n0 = blockIdx.x * 128;
    const int m0 = blockIdx.y * 128;

    float acc[2][8][4];
    #pragma unroll
    for (int a = 0; a < 2; a++)
        #pragma unroll
        for (int b = 0; b < 8; b++)
            #pragma unroll
            for (int c = 0; c < 4; c++) acc[a][b][c] = 0.0f;

    hmma_tile(sb, m0, n0, tid, g_V0h, g_V1Th, acc);

    const int warpM = wid & 3;
    const int warpN = wid >> 2;
    const int rbase = m0 + warpM * 32 + (lane >> 2);
    const int cbase = n0 + warpN * 64 + (lane & 3) * 2;
    #pragma unroll
    for (int t = 0; t < 8; t++) {
        const int col = cbase + t * 8;
        #pragma unroll
        for (int mi = 0; mi < 2; mi++) {
            const int r0 = rbase + mi * 16;
            __half2 h0, h1;
            h0.x = __float2half(acc[mi][t][0]); h0.y = __float2half(acc[mi][t][1]);
            h1.x = __float2half(acc[mi][t][2]); h1.y = __float2half(acc[mi][t][3]);
            *(__half2*)&g_Uh[(size_t)r0 * N_DIM + col]       = h0;
            *(__half2*)&g_Uh[(size_t)(r0 + 8) * N_DIM + col] = h1;
        }
    }
}

// ---------------- kernel 4: main fp16 GEMM out = x @ U^T + bias ----------------
__global__ void __launch_bounds__(256, 2) gemm_kernel(float* __restrict__ out,
                                                      const float* __restrict__ bias) {
    extern __shared__ char smem[];
    const uint32_t sb = smem_u32(smem);
    const int tid = threadIdx.x;
    const int lane = tid & 31;
    const int wid  = tid >> 5;
    const int n0 = blockIdx.x * 128;
    const int m0 = blockIdx.y * 128;

    float acc[2][8][4];
    #pragma unroll
    for (int a = 0; a < 2; a++)
        #pragma unroll
        for (int b = 0; b < 8; b++)
            #pragma unroll
            for (int c = 0; c < 4; c++) acc[a][b][c] = 0.0f;

    hmma_tile(sb, m0, n0, tid, g_xh, g_Uh, acc);

    const int warpM = wid & 3;
    const int warpN = wid >> 2;
    const int rbase = m0 + warpM * 32 + (lane >> 2);
    const int cbase = n0 + warpN * 64 + (lane & 3) * 2;
    #pragma unroll
    for (int t = 0; t < 8; t++) {
        const int col = cbase + t * 8;
        const float2 bv = __ldg((const float2*)&bias[col]);
        #pragma unroll
        for (int mi = 0; mi < 2; mi++) {
            const int r0 = rbase + mi * 16;
            float2 v0, v1;
            v0.x = acc[mi][t][0] + bv.x; v0.y = acc[mi][t][1] + bv.y;
            v1.x = acc[mi][t][2] + bv.x; v1.y = acc[mi][t][3] + bv.y;
            *(float2*)&out[(size_t)r0 * N_DIM + col]       = v0;
            *(float2*)&out[(size_t)(r0 + 8) * N_DIM + col] = v1;
        }
    }
}

// ---------------- launch ----------------
extern "C" void kernel_launch(void* const* d_in, const int* in_sizes, int n_in,
                              void* d_out, int out_size) {
    const float* x = nullptr;
    const float* angles = nullptr;
    const float* bias = nullptr;
    const int*   blocks = nullptr;
    for (int i = 0; i < n_in; i++) {
        const long sz = in_sizes[i];
        if      (sz == (long)BATCH_DIM * N_DIM)  x      = (const float*)d_in[i];
        else if (sz == (long)NROUND * NPAIR)     angles = (const float*)d_in[i];
        else if (sz == (long)N_DIM)              bias   = (const float*)d_in[i];
        else if (sz == (long)NROUND * NPAIR * 2) blocks = (const int*)d_in[i];
    }
    float* out = (float*)d_out;

    sched_kernel<<<NROUND, NPAIR>>>(blocks, angles);
    build_split_kernel<<<512, 256>>>((const float4*)x);
    cudaFuncSetAttribute(fixup_kernel, cudaFuncAttributeMaxDynamicSharedMemorySize, GEMM_SMEM);
    fixup_kernel<<<dim3(4, 4), 256, GEMM_SMEM>>>();
    cudaFuncSetAttribute(gemm_kernel, cudaFuncAttributeMaxDynamicSharedMemorySize, GEMM_SMEM);
    gemm_kernel<<<dim3(4, 128), 256, GEMM_SMEM>>>(out, bias);
}

// round 15
// speedup vs baseline: 1.3077x; 1.0486x over previous
#include <cuda_runtime.h>
#include <cuda_fp16.h>
#include <cstdint>
#include <cstddef>

#define N_DIM     512
#define BATCH_DIM 16384
#define NROUND    511
#define NPAIR     256
#define RPB       4                 // rows per build block
#define SEG0_END  256               // seg0 = rounds [0,256), seg1 = [256,511)

// ---------------- scratch (static device globals; no runtime allocation) ----------------
__device__ __align__(16) uint32_t g_sched[NROUND * NPAIR];   // packed (i | j<<16), oriented
__device__ __align__(16) float2   g_cs  [NROUND * NPAIR];    // matching (cos, sin')
__device__ __align__(16) __half   g_V0h [N_DIM * N_DIM];     // V0, fp16, (m,k) K-major
__device__ __align__(16) __half   g_V1Th[N_DIM * N_DIM];     // V1^T, fp16: [n*512+k] = V1[k][n]
__device__ __align__(16) __half   g_Uh  [N_DIM * N_DIM];     // U = V0*V1, fp16 row-major
__device__ __align__(16) __half   g_xh[(size_t)BATCH_DIM * N_DIM];

// ---------------- helpers ----------------
__device__ __forceinline__ uint32_t smem_u32(const void* p) {
    uint32_t a;
    asm("{ .reg .u64 t; cvta.to.shared.u64 t, %1; cvt.u32.u64 %0, t; }" : "=r"(a) : "l"(p));
    return a;
}

__device__ __forceinline__ void cp_async16(uint32_t s, const void* g) {
    asm volatile("cp.async.cg.shared.global [%0], [%1], 16;" :: "r"(s), "l"(g) : "memory");
}

__device__ __forceinline__ void ldm_x4(uint32_t* r, uint32_t addr) {
    asm volatile("ldmatrix.sync.aligned.m8n8.x4.shared.b16 {%0,%1,%2,%3}, [%4];"
                 : "=r"(r[0]), "=r"(r[1]), "=r"(r[2]), "=r"(r[3]) : "r"(addr));
}

__device__ __forceinline__ void mma16816(float* d, const uint32_t* a, uint32_t b0, uint32_t b1) {
    asm volatile(
        "mma.sync.aligned.m16n8k16.row.col.f32.f16.f16.f32 "
        "{%0,%1,%2,%3}, {%4,%5,%6,%7}, {%8,%9}, {%0,%1,%2,%3};"
        : "+f"(d[0]), "+f"(d[1]), "+f"(d[2]), "+f"(d[3])
        : "r"(a[0]), "r"(a[1]), "r"(a[2]), "r"(a[3]), "r"(b0), "r"(b1));
}

// ---------------- kernel 1: conflict-aware scheduling + sincos ----------------
__global__ void __launch_bounds__(NPAIR) sched_kernel(const int* __restrict__ blocks,
                                                      const float* __restrict__ angles) {
    __shared__ int  cnt[32];
    __shared__ int  jflag[8 * 32];
    __shared__ unsigned char taken[NPAIR];
    __shared__ int  sfree[NPAIR];
    __shared__ int  nfree, ovfp;
    const int r = blockIdx.x;
    const int t = threadIdx.x;
    if (t < 32) cnt[t] = 0;
    jflag[t] = 0;
    taken[t] = 0;
    if (t == 0) { nfree = 0; ovfp = 0; }
    __syncthreads();

    const int i = blocks[(r * NPAIR + t) * 2];
    const int j = blocks[(r * NPAIR + t) * 2 + 1];
    float s, c;
    sincosf(angles[r * NPAIR + t], &s, &c);
    const int bi = i & 31, bj = j & 31;

    const int oA = cnt[bi], oB = cnt[bj];
    const int fA = (oA < 8) && (jflag[oA * 32 + bj] == 0);
    const int fB = (oB < 8) && (jflag[oB * 32 + bi] == 0);
    int pref_first;
    if (fA != fB) pref_first = fA;
    else          pref_first = (oA <= oB);

    int slot = -1, swapped = 0;
    const int b0 = pref_first ? bi : bj;
    const int jb0 = pref_first ? bj : bi;
    int occ = atomicAdd(&cnt[b0], 1);
    if (occ < 8) {
        slot = occ * 32 + b0; swapped = pref_first ? 0 : 1;
        jflag[occ * 32 + jb0] = 1;
    } else {
        atomicSub(&cnt[b0], 1);
        const int b1 = pref_first ? bj : bi;
        const int jb1 = pref_first ? bi : bj;
        occ = atomicAdd(&cnt[b1], 1);
        if (occ < 8) {
            slot = occ * 32 + b1; swapped = pref_first ? 1 : 0;
            jflag[occ * 32 + jb1] = 1;
        } else atomicSub(&cnt[b1], 1);
    }
    if (slot >= 0) taken[slot] = 1;
    __syncthreads();
    if (!taken[t]) { int k = atomicAdd(&nfree, 1); sfree[k] = t; }
    __syncthreads();
    if (slot < 0) { int k = atomicAdd(&ovfp, 1); slot = sfree[k]; }

    const uint32_t ii = (uint32_t)(swapped ? j : i);
    const uint32_t jj = (uint32_t)(swapped ? i : j);
    g_sched[r * NPAIR + slot] = ii | (jj << 16);
    g_cs  [r * NPAIR + slot] = make_float2(c, swapped ? -s : s);
}

// ---------------- kernel 2 (fused): build V0 / V1^T (fp16)  +  cast x to fp16 ----------------
__global__ void __launch_bounds__(256) build_split_kernel(const float4* __restrict__ x4) {
    const int t = threadIdx.x;
    if (blockIdx.x < 256) {
        __shared__ float rows[RPB][N_DIM];
        const int seg   = blockIdx.x >> 7;                  // 0 or 1
        const int obase = (blockIdx.x & 127) * RPB;
        const int r0 = seg ? SEG0_END : 0;
        const int r1 = seg ? NROUND   : SEG0_END;
        #pragma unroll
        for (int q = 0; q < RPB; q++) {
            rows[q][t]       = (t == obase + q)       ? 1.0f : 0.0f;
            rows[q][t + 256] = (t + 256 == obase + q) ? 1.0f : 0.0f;
        }
        uint32_t id = g_sched[r0 * NPAIR + t];
        float2   cs = g_cs[r0 * NPAIR + t];
        __syncthreads();
        for (int r = r0; r < r1; r++) {
            const int nidx = (r + 1 < r1) ? (r + 1) * NPAIR + t : r0 * NPAIR + t;
            const uint32_t id_n = g_sched[nidx];
            const float2   cs_n = g_cs[nidx];
            const int i = (int)(id & 0xFFFFu);
            const int j = (int)(id >> 16);
            #pragma unroll
            for (int q = 0; q < RPB; q++) {
                const float ui = rows[q][i];
                const float uj = rows[q][j];
                rows[q][i] = fmaf(cs.x, ui, cs.y * uj);
                rows[q][j] = fmaf(cs.x, uj, -(cs.y * ui));
            }
            __syncthreads();
            id = id_n; cs = cs_n;
        }
        if (seg == 0) {
            #pragma unroll
            for (int q = 0; q < RPB; q++)
                for (int c = t; c < N_DIM; c += 256)
                    g_V0h[(obase + q) * N_DIM + c] = __float2half(rows[q][c]);
        } else {
            #pragma unroll
            for (int cc = t; cc < N_DIM; cc += 256) {
                __half2 p0, p1;
                p0.x = __float2half(rows[0][cc]); p0.y = __float2half(rows[1][cc]);
                p1.x = __float2half(rows[2][cc]); p1.y = __float2half(rows[3][cc]);
                __half2* dst = (__half2*)&g_V1Th[cc * N_DIM + obase];
                dst[0] = p0; dst[1] = p1;
            }
        }
    } else {
        const int bs = blockIdx.x - 256;                    // 0..255
        const int base = bs * 8192;
        #pragma unroll 4
        for (int k = 0; k < 32; k++) {
            const int idx = base + k * 256 + t;
            const float4 v = x4[idx];
            __half2 a, b;
            a.x = __float2half(v.x); a.y = __float2half(v.y);
            b.x = __float2half(v.z); b.y = __float2half(v.w);
            ((__half2*)g_xh)[2 * idx]     = a;
            ((__half2*)g_xh)[2 * idx + 1] = b;
        }
    }
}

// ---------------- shared HMMA tile machinery: CTA tile 64(M) x 128(N), 128 thr ----------------
// 4 warps: warpM in {0,1}, warpN in {0,1}; warp tile 32x64. 2-stage cp.async pipeline,
// 4 CTAs/SM (55 KB smem, ~122 regs) -> 16 warps in 4 independent barrier domains.
#define KC        64
#define PITCH     144
#define ATILE_SB  (64 * PITCH)              // 9216 B
#define BTILE_SB  (128 * PITCH)             // 18432 B
#define STAGE_SB  (ATILE_SB + BTILE_SB)     // 27648 B
#define NSTAGE    2
#define GEMM_SMEM (NSTAGE * STAGE_SB)       // 55296 B
#define NCHUNK    8

__device__ __forceinline__ void issue_chunk_gen(uint32_t sbase, int i, int m0, int n0, int tid,
                                                const __half* __restrict__ Abuf,
                                                const __half* __restrict__ Bbuf) {
    if (i < NCHUNK) {
        const __half* gA = Abuf + (size_t)m0 * N_DIM + i * KC;
        const __half* gB = Bbuf + (size_t)n0 * N_DIM + i * KC;
        const uint32_t stage = sbase + (uint32_t)(i & 1) * STAGE_SB;
        #pragma unroll
        for (int tt = 0; tt < 4; tt++) {                    // A: 64 rows -> 512 x 16B
            const int idx = tid + tt * 128;
            const int row = idx >> 3, seg = idx & 7;
            cp_async16(stage + (uint32_t)(row * PITCH + seg * 16),
                       gA + (size_t)row * N_DIM + seg * 8);
        }
        #pragma unroll
        for (int tt = 0; tt < 8; tt++) {                    // B: 128 rows -> 1024 x 16B
            const int idx = tid + tt * 128;
            const int row = idx >> 3, seg = idx & 7;
            cp_async16(stage + ATILE_SB + (uint32_t)(row * PITCH + seg * 16),
                       gB + (size_t)row * N_DIM + seg * 8);
        }
    }
    asm volatile("cp.async.commit_group;" ::: "memory");
}

// acc[2][8][4] = A[m0:+64,:] * B[n0:+128,:]^T over K=512 (per-warp 32x64 slice).
__device__ __forceinline__ void hmma_tile(uint32_t sb, int m0, int n0, int tid,
                                          const __half* __restrict__ Abuf,
                                          const __half* __restrict__ Bbuf,
                                          float acc[2][8][4]) {
    const int lane  = tid & 31;
    const int wid   = tid >> 5;
    const int warpM = wid & 1;
    const int warpN = wid >> 1;
    const int lrow = lane & 15;
    const int loct = lane >> 4;

    issue_chunk_gen(sb, 0, m0, n0, tid, Abuf, Bbuf);
    issue_chunk_gen(sb, 1, m0, n0, tid, Abuf, Bbuf);

    for (int i = 0; i < NCHUNK; i++) {
        asm volatile("cp.async.wait_group 1;" ::: "memory");   // chunk i resident
        __syncthreads();

        const uint32_t stage = sb + (uint32_t)(i & 1) * STAGE_SB;
        const uint32_t sA = stage + (uint32_t)((warpM * 32 + lrow) * PITCH);
        const uint32_t sB = stage + ATILE_SB + (uint32_t)((warpN * 64 + lrow) * PITCH);

        #pragma unroll
        for (int ks = 0; ks < 4; ks++) {
            const uint32_t koff = (uint32_t)(ks * 32 + loct * 16);
            uint32_t afr[2][4], bfr[4][4];
            #pragma unroll
            for (int mi = 0; mi < 2; mi++)
                ldm_x4(afr[mi], sA + (uint32_t)(mi * 16 * PITCH) + koff);
            #pragma unroll
            for (int nj = 0; nj < 4; nj++)
                ldm_x4(bfr[nj], sB + (uint32_t)(nj * 16 * PITCH) + koff);
            #pragma unroll
            for (int mi = 0; mi < 2; mi++)
                #pragma unroll
                for (int t = 0; t < 8; t++) {
                    const int nj = t >> 1, hl = t & 1;
                    mma16816(acc[mi][t], afr[mi], bfr[nj][hl], bfr[nj][hl + 2]);
                }
        }
        __syncthreads();                                       // all warps done with stage i&1
        issue_chunk_gen(sb, i + 2, m0, n0, tid, Abuf, Bbuf);   // safe overwrite
    }
}

// ---------------- kernel 3: fixup  U = V0 * V1  via HMMA (32 CTAs) ----------------
__global__ void __launch_bounds__(128, 4) fixup_kernel() {
    extern __shared__ char smem[];
    const uint32_t sb = smem_u32(smem);
    const int tid = threadIdx.x;
    const int lane = tid & 31;
    const int wid  = tid >> 5;
    const int n0 = blockIdx.x * 128;
    const int m0 = blockIdx.y * 64;

    float acc[2][8][4];
    #pragma unroll
    for (int a = 0; a < 2; a++)
        #pragma unroll
        for (int b = 0; b < 8; b++)
            #pragma unroll
            for (int c = 0; c < 4; c++) acc[a][b][c] = 0.0f;

    hmma_tile(sb, m0, n0, tid, g_V0h, g_V1Th, acc);

    const int warpM = wid & 1;
    const int warpN = wid >> 1;
    const int rbase = m0 + warpM * 32 + (lane >> 2);
    const int cbase = n0 + warpN * 64 + (lane & 3) * 2;
    #pragma unroll
    for (int t = 0; t < 8; t++) {
        const int col = cbase + t * 8;
        #pragma unroll
        for (int mi = 0; mi < 2; mi++) {
            const int r0 = rbase + mi * 16;
            __half2 h0, h1;
            h0.x = __float2half(acc[mi][t][0]); h0.y = __float2half(acc[mi][t][1]);
            h1.x = __float2half(acc[mi][t][2]); h1.y = __float2half(acc[mi][t][3]);
            *(__half2*)&g_Uh[(size_t)r0 * N_DIM + col]       = h0;
            *(__half2*)&g_Uh[(size_t)(r0 + 8) * N_DIM + col] = h1;
        }
    }
}

// ---------------- kernel 4: main fp16 GEMM out = x @ U^T + bias (1024 CTAs) ----------------
__global__ void __launch_bounds__(128, 4) gemm_kernel(float* __restrict__ out,
                                                      const float* __restrict__ bias) {
    extern __shared__ char smem[];
    const uint32_t sb = smem_u32(smem);
    const int tid = threadIdx.x;
    const int lane = tid & 31;
    const int wid  = tid >> 5;
    const int n0 = blockIdx.x * 128;
    const int m0 = blockIdx.y * 64;

    float acc[2][8][4];
    #pragma unroll
    for (int a = 0; a < 2; a++)
        #pragma unroll
        for (int b = 0; b < 8; b++)
            #pragma unroll
            for (int c = 0; c < 4; c++) acc[a][b][c] = 0.0f;

    hmma_tile(sb, m0, n0, tid, g_xh, g_Uh, acc);

    const int warpM = wid & 1;
    const int warpN = wid >> 1;
    const int rbase = m0 + warpM * 32 + (lane >> 2);
    const int cbase = n0 + warpN * 64 + (lane & 3) * 2;
    #pragma unroll
    for (int t = 0; t < 8; t++) {
        const int col = cbase + t * 8;
        const float2 bv = __ldg((const float2*)&bias[col]);
        #pragma unroll
        for (int mi = 0; mi < 2; mi++) {
            const int r0 = rbase + mi * 16;
            float2 v0, v1;
            v0.x = acc[mi][t][0] + bv.x; v0.y = acc[mi][t][1] + bv.y;
            v1.x = acc[mi][t][2] + bv.x; v1.y = acc[mi][t][3] + bv.y;
            *(float2*)&out[(size_t)r0 * N_DIM + col]       = v0;
            *(float2*)&out[(size_t)(r0 + 8) * N_DIM + col] = v1;
        }
    }
}

// ---------------- launch ----------------
extern "C" void kernel_launch(void* const* d_in, const int* in_sizes, int n_in,
                              void* d_out, int out_size) {
    const float* x = nullptr;
    const float* angles = nullptr;
    const float* bias = nullptr;
    const int*   blocks = nullptr;
    for (int i = 0; i < n_in; i++) {
        const long sz = in_sizes[i];
        if      (sz == (long)BATCH_DIM * N_DIM)  x      = (const float*)d_in[i];
        else if (sz == (long)NROUND * NPAIR)     angles = (const float*)d_in[i];
        else if (sz == (long)N_DIM)              bias   = (const float*)d_in[i];
        else if (sz == (long)NROUND * NPAIR * 2) blocks = (const int*)d_in[i];
    }
    float* out = (float*)d_out;

    sched_kernel<<<NROUND, NPAIR>>>(blocks, angles);
    build_split_kernel<<<512, 256>>>((const float4*)x);
    cudaFuncSetAttribute(fixup_kernel, cudaFuncAttributeMaxDynamicSharedMemorySize, GEMM_SMEM);
    fixup_kernel<<<dim3(4, 8), 128, GEMM_SMEM>>>();
    cudaFuncSetAttribute(gemm_kernel, cudaFuncAttributeMaxDynamicSharedMemorySize, GEMM_SMEM);
    gemm_kernel<<<dim3(4, 256), 128, GEMM_SMEM>>>(out, bias);
}